// round 4
// baseline (speedup 1.0000x reference)
#include <cuda_runtime.h>
#include <math.h>
#include <stdint.h>

#define H        4
#define NN       10000
#define EMB      128
#define NB       4096
#define NQ       8192          // queries per head: [src(4096) | dst(4096)]
#define BQ       128           // queries per block
#define BN       64            // node tile
#define NTILES   ((NN + BN - 1) / BN)
#define TOPK     9
#define SB_LD    (BN + 1)      // padded row for conflict-free scan

// dynamic smem layout (floats):
//   Qs [EMB][BQ]       = 16384
//   Ns [EMB][BN]       =  8192
//   Sb [BQ][SB_LD]     =  8320
//   y2s[BN]            =    64
#define SMEM_FLOATS (EMB*BQ + EMB*BN + BQ*SB_LD + BN)
#define SMEM_BYTES  (SMEM_FLOATS * 4)

__device__ float g_y2[H * NN];
__device__ int   g_samples[H * NQ * 8];

// ---------------------------------------------------------------------------
// K1: per-(head,node) squared norms. one warp per row.
// ---------------------------------------------------------------------------
__global__ void norms_kernel(const float* __restrict__ embeds) {
    int gid  = blockIdx.x * 8 + (threadIdx.x >> 5);
    int lane = threadIdx.x & 31;
    if (gid >= H * NN) return;
    const float4* row = (const float4*)(embeds + (size_t)gid * EMB);
    float4 v = row[lane];
    float s = v.x*v.x + v.y*v.y + v.z*v.z + v.w*v.w;
    #pragma unroll
    for (int o = 16; o > 0; o >>= 1) s += __shfl_xor_sync(0xffffffffu, s, o);
    if (lane == 0) g_y2[gid] = s;
}

// ---------------------------------------------------------------------------
// K2: fused GEMM + top-9. grid (NQ/BQ, H), 256 threads.
// Transposed smem tiles: Qs[k][q], Ns[k][n]. Thread (tq,tn) = (tid>>4, tid&15)
// computes an 8q x 4n micro-tile. key = y2[n] - 2*dot (rank-equivalent to d2).
// ---------------------------------------------------------------------------
__global__ __launch_bounds__(256, 1)
void knn_kernel(const float* __restrict__ embeds, const int* __restrict__ edges) {
    extern __shared__ float smem[];
    float* Qs  = smem;                 // [EMB][BQ]
    float* Ns  = Qs + EMB * BQ;        // [EMB][BN]
    float* Sb  = Ns + EMB * BN;        // [BQ][SB_LD]
    float* y2s = Sb + BQ * SB_LD;      // [BN]

    const int tid   = threadIdx.x;
    const int h     = blockIdx.y;
    const int qbase = blockIdx.x * BQ;
    const float* E  = embeds + (size_t)h * NN * EMB;

    // ---- gather query embeddings, store transposed ----
    {
        int q  = tid >> 1;
        int k0 = (tid & 1) * 64;
        int node = edges[qbase + q];   // flattened (2,4096) matches query order
        const float* row = E + (size_t)node * EMB + k0;
        #pragma unroll
        for (int i = 0; i < 64; i += 4) {
            float4 v = *(const float4*)(row + i);
            Qs[(k0 + i + 0) * BQ + q] = v.x;
            Qs[(k0 + i + 1) * BQ + q] = v.y;
            Qs[(k0 + i + 2) * BQ + q] = v.z;
            Qs[(k0 + i + 3) * BQ + q] = v.w;
        }
    }

    // ---- per-owner top-9 (ascending key; ties keep lower index == top_k) ----
    float bk[TOPK];
    int   bi[TOPK];
    #pragma unroll
    for (int r = 0; r < TOPK; r++) { bk[r] = 3.0e38f; bi[r] = 0; }

    const int tq = tid >> 4, tn = tid & 15;
    const int q0 = tq * 8,   n0 = tn * 4;

    for (int t = 0; t < NTILES; t++) {
        const int nbase = t * BN;
        __syncthreads();  // prev scan done; Ns free

        // ---- load node tile, transposed; pad OOB with 0 / huge norm ----
        {
            int n    = tid & 63;
            int k0   = (tid >> 6) * 32;
            int node = nbase + n;
            if (node < NN) {
                const float* row = E + (size_t)node * EMB + k0;
                #pragma unroll
                for (int i = 0; i < 32; i += 4) {
                    float4 v = *(const float4*)(row + i);
                    Ns[(k0 + i + 0) * BN + n] = v.x;
                    Ns[(k0 + i + 1) * BN + n] = v.y;
                    Ns[(k0 + i + 2) * BN + n] = v.z;
                    Ns[(k0 + i + 3) * BN + n] = v.w;
                }
            } else {
                #pragma unroll
                for (int i = 0; i < 32; i++) Ns[(k0 + i) * BN + n] = 0.0f;
            }
            if (tid < BN)
                y2s[tid] = (nbase + tid < NN) ? g_y2[h * NN + nbase + tid] : 3.0e37f;
        }
        __syncthreads();

        // ---- 8x4 register micro-tile GEMM ----
        float acc[8][4];
        #pragma unroll
        for (int i = 0; i < 8; i++)
            #pragma unroll
            for (int j = 0; j < 4; j++) acc[i][j] = 0.0f;

        #pragma unroll 8
        for (int k = 0; k < EMB; k++) {
            float4 qa = *(const float4*)(Qs + k * BQ + q0);
            float4 qb = *(const float4*)(Qs + k * BQ + q0 + 4);
            float4 nv = *(const float4*)(Ns + k * BN + n0);
            float qv[8]  = {qa.x, qa.y, qa.z, qa.w, qb.x, qb.y, qb.z, qb.w};
            float nvv[4] = {nv.x, nv.y, nv.z, nv.w};
            #pragma unroll
            for (int i = 0; i < 8; i++)
                #pragma unroll
                for (int j = 0; j < 4; j++) acc[i][j] += qv[i] * nvv[j];
        }

        // ---- write keys to scan buffer ----
        float yv[4];
        #pragma unroll
        for (int j = 0; j < 4; j++) yv[j] = y2s[n0 + j];
        #pragma unroll
        for (int i = 0; i < 8; i++)
            #pragma unroll
            for (int j = 0; j < 4; j++)
                Sb[(q0 + i) * SB_LD + n0 + j] = yv[j] - 2.0f * acc[i][j];
        __syncthreads();

        // ---- owner threads scan 64 keys; rare sorted insertion ----
        if (tid < BQ) {
            const float* row = Sb + tid * SB_LD;
            #pragma unroll 4
            for (int n = 0; n < BN; n++) {
                float key = row[n];
                if (key < bk[TOPK - 1]) {      // strict <: ties keep lower index
                    bk[TOPK - 1] = key;
                    bi[TOPK - 1] = nbase + n;
                    #pragma unroll
                    for (int r = TOPK - 1; r > 0; r--) {
                        if (bk[r] < bk[r - 1]) {
                            float tk = bk[r]; bk[r] = bk[r - 1]; bk[r - 1] = tk;
                            int   ti = bi[r]; bi[r] = bi[r - 1]; bi[r - 1] = ti;
                        }
                    }
                }
            }
        }
    }

    // ---- emit ranks 1..8 (rank 0 == self) ----
    if (tid < BQ) {
        int gq = qbase + tid;
        int* out = g_samples + ((size_t)h * NQ + gq) * 8;
        #pragma unroll
        for (int r = 1; r < TOPK; r++) out[r - 1] = bi[r];
    }
}

// ---------------------------------------------------------------------------
// K3: epilogue. one block per batch edge, one warp per head.
// logits = diff . field[other] + U*(2*adj-1);  dist = ||diff||;
// 24-way softmax (8 zero-logit / unit-dist sentinels), head mean, sigmoid.
// ---------------------------------------------------------------------------
__global__ void epilogue_kernel(const float* __restrict__ embeds,
                                const float* __restrict__ field,
                                const float* __restrict__ unc,
                                const float* __restrict__ adj,
                                const int*   __restrict__ edges,
                                float*       __restrict__ out) {
    const int b    = blockIdx.x;
    const int h    = threadIdx.x >> 5;
    const int lane = threadIdx.x & 31;
    const int src  = edges[b];
    const int dst  = edges[NB + b];
    const float U  = unc[0];

    __shared__ float s_logit[H][16];
    __shared__ float s_dist[H][16];
    __shared__ float s_soft[H];

    const float* Eh = embeds + (size_t)h * NN * EMB;
    const float* Fh = field  + (size_t)h * NN * EMB;

    #pragma unroll
    for (int side = 0; side < 2; side++) {
        const int n     = (side == 0) ? src : dst;
        const int other = (side == 0) ? dst : src;
        const int* samp = g_samples + ((size_t)h * NQ + side * NB + b) * 8;
        float4 xn = ((const float4*)(Eh + (size_t)n * EMB))[lane];
        float4 gv = ((const float4*)(Fh + (size_t)other * EMB))[lane];
        for (int k = 0; k < 8; k++) {
            int s = samp[k];
            float4 es = ((const float4*)(Eh + (size_t)s * EMB))[lane];
            float dx = xn.x - es.x, dy = xn.y - es.y;
            float dz = xn.z - es.z, dw = xn.w - es.w;
            float dot = dx * gv.x + dy * gv.y + dz * gv.z + dw * gv.w;
            float ss  = dx * dx + dy * dy + dz * dz + dw * dw;
            #pragma unroll
            for (int o = 16; o > 0; o >>= 1) {
                dot += __shfl_xor_sync(0xffffffffu, dot, o);
                ss  += __shfl_xor_sync(0xffffffffu, ss,  o);
            }
            if (lane == 0) {
                float a = (side == 0) ? adj[(size_t)s * NN + other]
                                      : adj[(size_t)other * NN + s];
                s_logit[h][side * 8 + k] = dot + U * (a * 2.0f - 1.0f);
                s_dist [h][side * 8 + k] = sqrtf(ss);
            }
        }
    }
    __syncwarp();

    // softmax over 16 neighbors + 8 sentinels (logit 0, dist 1 -> weight e^{-m})
    float w  = -3.0e38f, lg = 0.0f;
    if (lane < 16) { lg = s_logit[h][lane]; w = 1.0f - s_dist[h][lane]; }
    float m = w;
    #pragma unroll
    for (int o = 16; o > 0; o >>= 1) m = fmaxf(m, __shfl_xor_sync(0xffffffffu, m, o));
    m = fmaxf(m, 0.0f);
    float e   = (lane < 16) ? expf(w - m) : 0.0f;
    float num = e * lg;
    float den = e;
    #pragma unroll
    for (int o = 16; o > 0; o >>= 1) {
        num += __shfl_xor_sync(0xffffffffu, num, o);
        den += __shfl_xor_sync(0xffffffffu, den, o);
    }
    den += 8.0f * expf(-m);
    if (lane == 0) s_soft[h] = num / den;

    __syncthreads();
    if (threadIdx.x == 0) {
        float s = (s_soft[0] + s_soft[1] + s_soft[2] + s_soft[3]) * 0.25f;
        out[b] = 1.0f / (1.0f + expf(-s));
    }
}

// ---------------------------------------------------------------------------
extern "C" void kernel_launch(void* const* d_in, const int* in_sizes, int n_in,
                              void* d_out, int out_size) {
    (void)in_sizes; (void)n_in; (void)out_size;
    const float* embeds = (const float*)d_in[0];   // (4,10000,128) f32
    const float* field  = (const float*)d_in[1];   // (4,10000,128) f32
    const float* unc    = (const float*)d_in[2];   // (1,1,1) f32
    const float* adj    = (const float*)d_in[3];   // (10000,10000) f32
    const int*   edges  = (const int*)  d_in[4];   // (2,4096) i32
    float* out = (float*)d_out;                    // (4096,) f32

    cudaFuncSetAttribute(knn_kernel,
                         cudaFuncAttributeMaxDynamicSharedMemorySize, SMEM_BYTES);

    norms_kernel<<<(H * NN) / 8, 256>>>(embeds);
    knn_kernel<<<dim3(NQ / BQ, H), 256, SMEM_BYTES>>>(embeds, edges);
    epilogue_kernel<<<NB, 128>>>(embeds, field, unc, adj, edges, out);
}

// round 5
// speedup vs baseline: 2.1095x; 2.1095x over previous
#include <cuda_runtime.h>
#include <math.h>
#include <stdint.h>

#define H        4
#define NN       10000
#define EMB      128
#define NB       4096
#define NQ       8192          // queries per head: [src(4096) | dst(4096)]
#define BQ       128           // queries per block
#define BN       128           // node tile
#define NTILES   ((NN + BN - 1) / BN)   // 79
#define TOPK     9
#define Q_LD     132           // padded: 132 % 32 == 4 -> conflict-free frags
#define N_LD     132
#define SB_LD    129           // odd -> conflict-free row scan

// dynamic smem (floats): Qs[BQ][Q_LD] + Ns[BN][N_LD] + Sb[BQ][SB_LD] + y2s[BN]
#define SMEM_FLOATS (BQ*Q_LD + BN*N_LD + BQ*SB_LD + BN)
#define SMEM_BYTES  (SMEM_FLOATS * 4)

__device__ float g_y2[H * NN];
__device__ int   g_samples[H * NQ * 8];

// ---------------------------------------------------------------------------
// K1: per-(head,node) squared norms. one warp per row.
// ---------------------------------------------------------------------------
__global__ void norms_kernel(const float* __restrict__ embeds) {
    int gid  = blockIdx.x * 8 + (threadIdx.x >> 5);
    int lane = threadIdx.x & 31;
    if (gid >= H * NN) return;
    const float4* row = (const float4*)(embeds + (size_t)gid * EMB);
    float4 v = row[lane];
    float s = v.x*v.x + v.y*v.y + v.z*v.z + v.w*v.w;
    #pragma unroll
    for (int o = 16; o > 0; o >>= 1) s += __shfl_xor_sync(0xffffffffu, s, o);
    if (lane == 0) g_y2[gid] = s;
}

// ---------------------------------------------------------------------------
// tf32 m16n8k8 mma (raw fp32 bits fed; HW truncates mantissa -> tf32)
// ---------------------------------------------------------------------------
__device__ __forceinline__ void mma_tf32(float* c, const uint32_t* a, const uint32_t* b) {
    asm volatile(
        "mma.sync.aligned.m16n8k8.row.col.f32.tf32.tf32.f32 "
        "{%0,%1,%2,%3}, {%4,%5,%6,%7}, {%8,%9}, {%0,%1,%2,%3};"
        : "+f"(c[0]), "+f"(c[1]), "+f"(c[2]), "+f"(c[3])
        : "r"(a[0]), "r"(a[1]), "r"(a[2]), "r"(a[3]), "r"(b[0]), "r"(b[1]));
}

// ---------------------------------------------------------------------------
// K2: tensor-core GEMM + fused top-9. grid (NQ/BQ, H), 128 threads (2x2 warps).
// Each warp: 64q x 64n via 4x8 m16n8k8 tf32 tiles, full K=128 in smem.
// key = y2[n] - 2*dot  (rank-equivalent to d2).
// ---------------------------------------------------------------------------
__global__ __launch_bounds__(128, 1)
void knn_kernel(const float* __restrict__ embeds, const int* __restrict__ edges) {
    extern __shared__ float smem[];
    float* Qs  = smem;                     // [BQ][Q_LD]
    float* Ns  = Qs + BQ * Q_LD;           // [BN][N_LD]
    float* Sb  = Ns + BN * N_LD;           // [BQ][SB_LD]
    float* y2s = Sb + BQ * SB_LD;          // [BN]

    const int tid   = threadIdx.x;
    const int lane  = tid & 31;
    const int wid   = tid >> 5;
    const int g     = lane >> 2;           // 0..7
    const int tg    = lane & 3;            // 0..3
    const int mw    = wid >> 1;            // warp row (0..1)
    const int nw    = wid & 1;             // warp col (0..1)
    const int R0    = mw * 64;
    const int C0    = nw * 64;

    const int h     = blockIdx.y;
    const int qbase = blockIdx.x * BQ;
    const float* E  = embeds + (size_t)h * NN * EMB;

    // ---- gather query tile: 4 threads per row for coalescing ----
    {
        int sub = tid & 3;
        #pragma unroll
        for (int p = 0; p < 4; p++) {
            int q = (tid >> 2) + p * 32;
            int node = edges[qbase + q];   // flattened (2,4096) matches query order
            const float4* row = (const float4*)(E + (size_t)node * EMB);
            float* dstf = Qs + q * Q_LD;
            #pragma unroll
            for (int i = 0; i < 8; i++) {
                float4 v = row[sub + 4 * i];
                *(float4*)(dstf + (sub + 4 * i) * 4) = v;
            }
        }
    }

    // ---- per-thread (row tid) top-9 ----
    float bk[TOPK];
    int   bi[TOPK];
    #pragma unroll
    for (int r = 0; r < TOPK; r++) { bk[r] = 3.0e38f; bi[r] = 0; }

    for (int t = 0; t < NTILES; t++) {
        const int nbase = t * BN;
        __syncthreads();                   // prev scan + prev k-loop done

        // ---- load node tile (row-major, padded) ----
        {
            int sub = tid & 3;
            #pragma unroll
            for (int p = 0; p < 4; p++) {
                int n = (tid >> 2) + p * 32;
                int node = nbase + n;
                float* dstf = Ns + n * N_LD;
                if (node < NN) {
                    const float4* row = (const float4*)(E + (size_t)node * EMB);
                    #pragma unroll
                    for (int i = 0; i < 8; i++) {
                        float4 v = row[sub + 4 * i];
                        *(float4*)(dstf + (sub + 4 * i) * 4) = v;
                    }
                } else {
                    #pragma unroll
                    for (int i = 0; i < 8; i++)
                        *(float4*)(dstf + (sub + 4 * i) * 4) = make_float4(0.f, 0.f, 0.f, 0.f);
                }
            }
            int node = nbase + tid;
            y2s[tid] = (node < NN) ? g_y2[h * NN + node] : 3.0e37f;
        }
        __syncthreads();                   // Ns/y2s visible

        // ---- tensor GEMM: 4x8 m16n8k8 tiles over K=128 ----
        float acc[4][8][4];
        #pragma unroll
        for (int mt = 0; mt < 4; mt++)
            #pragma unroll
            for (int nt = 0; nt < 8; nt++)
                #pragma unroll
                for (int r = 0; r < 4; r++) acc[mt][nt][r] = 0.0f;

        #pragma unroll 4
        for (int kk = 0; kk < EMB; kk += 8) {
            uint32_t a[4][4], b[8][2];
            #pragma unroll
            for (int mt = 0; mt < 4; mt++) {
                const float* p0 = Qs + (R0 + mt * 16 + g) * Q_LD + kk + tg;
                const float* p1 = p0 + 8 * Q_LD;
                a[mt][0] = __float_as_uint(p0[0]);
                a[mt][1] = __float_as_uint(p1[0]);
                a[mt][2] = __float_as_uint(p0[4]);
                a[mt][3] = __float_as_uint(p1[4]);
            }
            #pragma unroll
            for (int nt = 0; nt < 8; nt++) {
                const float* pb = Ns + (C0 + nt * 8 + g) * N_LD + kk + tg;
                b[nt][0] = __float_as_uint(pb[0]);
                b[nt][1] = __float_as_uint(pb[4]);
            }
            #pragma unroll
            for (int mt = 0; mt < 4; mt++)
                #pragma unroll
                for (int nt = 0; nt < 8; nt++)
                    mma_tf32(acc[mt][nt], a[mt], b[nt]);
        }

        // ---- write keys = y2 - 2*dot into scan buffer ----
        #pragma unroll
        for (int nt = 0; nt < 8; nt++) {
            int col = C0 + nt * 8 + tg * 2;
            float y0 = y2s[col], y1 = y2s[col + 1];
            #pragma unroll
            for (int mt = 0; mt < 4; mt++) {
                int row = R0 + mt * 16 + g;
                Sb[row * SB_LD + col]           = y0 - 2.0f * acc[mt][nt][0];
                Sb[row * SB_LD + col + 1]       = y1 - 2.0f * acc[mt][nt][1];
                Sb[(row + 8) * SB_LD + col]     = y0 - 2.0f * acc[mt][nt][2];
                Sb[(row + 8) * SB_LD + col + 1] = y1 - 2.0f * acc[mt][nt][3];
            }
        }
        __syncthreads();                   // Sb visible

        // ---- scan own row; rare sorted insertion (strict < keeps lower idx) ----
        {
            const float* rowp = Sb + tid * SB_LD;
            #pragma unroll 4
            for (int n = 0; n < BN; n++) {
                float key = rowp[n];
                if (key < bk[TOPK - 1]) {
                    bk[TOPK - 1] = key;
                    bi[TOPK - 1] = nbase + n;
                    #pragma unroll
                    for (int r = TOPK - 1; r > 0; r--) {
                        if (bk[r] < bk[r - 1]) {
                            float tk = bk[r]; bk[r] = bk[r - 1]; bk[r - 1] = tk;
                            int   ti = bi[r]; bi[r] = bi[r - 1]; bi[r - 1] = ti;
                        }
                    }
                }
            }
        }
    }

    // ---- emit ranks 1..8 (rank 0 == self) ----
    {
        int gq = qbase + tid;
        int* out = g_samples + ((size_t)h * NQ + gq) * 8;
        #pragma unroll
        for (int r = 1; r < TOPK; r++) out[r - 1] = bi[r];
    }
}

// ---------------------------------------------------------------------------
// K3: epilogue. one block per batch edge, one warp per head. Exact fp32.
// ---------------------------------------------------------------------------
__global__ void epilogue_kernel(const float* __restrict__ embeds,
                                const float* __restrict__ field,
                                const float* __restrict__ unc,
                                const float* __restrict__ adj,
                                const int*   __restrict__ edges,
                                float*       __restrict__ out) {
    const int b    = blockIdx.x;
    const int h    = threadIdx.x >> 5;
    const int lane = threadIdx.x & 31;
    const int src  = edges[b];
    const int dst  = edges[NB + b];
    const float U  = unc[0];

    __shared__ float s_logit[H][16];
    __shared__ float s_dist[H][16];
    __shared__ float s_soft[H];

    const float* Eh = embeds + (size_t)h * NN * EMB;
    const float* Fh = field  + (size_t)h * NN * EMB;

    #pragma unroll
    for (int side = 0; side < 2; side++) {
        const int n     = (side == 0) ? src : dst;
        const int other = (side == 0) ? dst : src;
        const int* samp = g_samples + ((size_t)h * NQ + side * NB + b) * 8;
        float4 xn = ((const float4*)(Eh + (size_t)n * EMB))[lane];
        float4 gv = ((const float4*)(Fh + (size_t)other * EMB))[lane];
        for (int k = 0; k < 8; k++) {
            int s = samp[k];
            float4 es = ((const float4*)(Eh + (size_t)s * EMB))[lane];
            float dx = xn.x - es.x, dy = xn.y - es.y;
            float dz = xn.z - es.z, dw = xn.w - es.w;
            float dot = dx * gv.x + dy * gv.y + dz * gv.z + dw * gv.w;
            float ss  = dx * dx + dy * dy + dz * dz + dw * dw;
            #pragma unroll
            for (int o = 16; o > 0; o >>= 1) {
                dot += __shfl_xor_sync(0xffffffffu, dot, o);
                ss  += __shfl_xor_sync(0xffffffffu, ss,  o);
            }
            if (lane == 0) {
                float a = (side == 0) ? adj[(size_t)s * NN + other]
                                      : adj[(size_t)other * NN + s];
                s_logit[h][side * 8 + k] = dot + U * (a * 2.0f - 1.0f);
                s_dist [h][side * 8 + k] = sqrtf(ss);
            }
        }
    }
    __syncwarp();

    // softmax over 16 neighbors + 8 sentinels (logit 0, dist 1)
    float w  = -3.0e38f, lg = 0.0f;
    if (lane < 16) { lg = s_logit[h][lane]; w = 1.0f - s_dist[h][lane]; }
    float m = w;
    #pragma unroll
    for (int o = 16; o > 0; o >>= 1) m = fmaxf(m, __shfl_xor_sync(0xffffffffu, m, o));
    m = fmaxf(m, 0.0f);
    float e   = (lane < 16) ? expf(w - m) : 0.0f;
    float num = e * lg;
    float den = e;
    #pragma unroll
    for (int o = 16; o > 0; o >>= 1) {
        num += __shfl_xor_sync(0xffffffffu, num, o);
        den += __shfl_xor_sync(0xffffffffu, den, o);
    }
    den += 8.0f * expf(-m);
    if (lane == 0) s_soft[h] = num / den;

    __syncthreads();
    if (threadIdx.x == 0) {
        float s = (s_soft[0] + s_soft[1] + s_soft[2] + s_soft[3]) * 0.25f;
        out[b] = 1.0f / (1.0f + expf(-s));
    }
}

// ---------------------------------------------------------------------------
extern "C" void kernel_launch(void* const* d_in, const int* in_sizes, int n_in,
                              void* d_out, int out_size) {
    (void)in_sizes; (void)n_in; (void)out_size;
    const float* embeds = (const float*)d_in[0];   // (4,10000,128) f32
    const float* field  = (const float*)d_in[1];   // (4,10000,128) f32
    const float* unc    = (const float*)d_in[2];   // (1,1,1) f32
    const float* adj    = (const float*)d_in[3];   // (10000,10000) f32
    const int*   edges  = (const int*)  d_in[4];   // (2,4096) i32
    float* out = (float*)d_out;                    // (4096,) f32

    cudaFuncSetAttribute(knn_kernel,
                         cudaFuncAttributeMaxDynamicSharedMemorySize, SMEM_BYTES);

    norms_kernel<<<(H * NN) / 8, 256>>>(embeds);
    knn_kernel<<<dim3(NQ / BQ, H), 128, SMEM_BYTES>>>(embeds, edges);
    epilogue_kernel<<<NB, 128>>>(embeds, field, unc, adj, edges, out);
}

// round 6
// speedup vs baseline: 3.5708x; 1.6928x over previous
#include <cuda_runtime.h>
#include <cuda_bf16.h>
#include <math.h>
#include <stdint.h>

#define H        4
#define NN       10000
#define EMB      128
#define NB       4096
#define NQ       8192          // queries per head: [src(4096) | dst(4096)]
#define BQ       128
#define BN       128
#define NTILES   ((NN + BN - 1) / BN)   // 79
#define TOPK     9
#define Q_LDE    136           // bf16 elems/row; 68 words/row; 68%32==4 -> conflict-free frags
#define N_LDE    136
#define SB_LD    131           // 3*row+c mod 32: conflict-free scan, <=2-way stores

// smem byte offsets
#define QS_BYTES   (BQ * Q_LDE * 2)            // 34816
#define NS_BYTES   (BN * N_LDE * 2)            // 34816 per buffer
#define SB_BYTES   (BQ * SB_LD * 4)            // 67072
#define OFF_NS     (QS_BYTES)
#define OFF_SB     (QS_BYTES + 2 * NS_BYTES)
#define OFF_Y2     (OFF_SB + SB_BYTES)
#define SMEM_BYTES (OFF_Y2 + 2 * BN * 4)       // 172544

__device__ __nv_bfloat16 g_ebf[(size_t)H * NN * EMB];
__device__ float g_y2[H * NN];
__device__ int   g_samples[H * NQ * 8];

// ---------------------------------------------------------------------------
// K1: convert embeds -> bf16, y2 from the ROUNDED values. one warp per row.
// ---------------------------------------------------------------------------
__global__ void prep_kernel(const float* __restrict__ embeds) {
    int gid  = blockIdx.x * 8 + (threadIdx.x >> 5);
    int lane = threadIdx.x & 31;
    if (gid >= H * NN) return;
    float4 v = ((const float4*)(embeds + (size_t)gid * EMB))[lane];
    __nv_bfloat162 p0 = __floats2bfloat162_rn(v.x, v.y);
    __nv_bfloat162 p1 = __floats2bfloat162_rn(v.z, v.w);
    __nv_bfloat162* dst = (__nv_bfloat162*)(g_ebf + (size_t)gid * EMB);
    dst[2 * lane]     = p0;
    dst[2 * lane + 1] = p1;
    float a = __bfloat162float(p0.x), b = __bfloat162float(p0.y);
    float c = __bfloat162float(p1.x), d = __bfloat162float(p1.y);
    float s = a * a + b * b + c * c + d * d;
    #pragma unroll
    for (int o = 16; o > 0; o >>= 1) s += __shfl_xor_sync(0xffffffffu, s, o);
    if (lane == 0) g_y2[gid] = s;
}

// ---------------------------------------------------------------------------
__device__ __forceinline__ void mma_bf16(float* c, const uint32_t* a, const uint32_t* b) {
    asm volatile(
        "mma.sync.aligned.m16n8k16.row.col.f32.bf16.bf16.f32 "
        "{%0,%1,%2,%3}, {%4,%5,%6,%7}, {%8,%9}, {%0,%1,%2,%3};"
        : "+f"(c[0]), "+f"(c[1]), "+f"(c[2]), "+f"(c[3])
        : "r"(a[0]), "r"(a[1]), "r"(a[2]), "r"(a[3]), "r"(b[0]), "r"(b[1]));
}

__device__ __forceinline__ void prefetch_tile(const __nv_bfloat16* __restrict__ Ebf,
                                              int h, int nbase, char* smem,
                                              int buf, int tid) {
    int row  = tid >> 1;
    int part = tid & 1;
    int node = nbase + row;
    int valid = (node < NN) ? 16 : 0;
    const char* src = (const char*)(Ebf + (size_t)((node < NN) ? node : 0) * EMB) + part * 128;
    uint32_t dst = (uint32_t)__cvta_generic_to_shared(
        smem + OFF_NS + buf * NS_BYTES + row * (N_LDE * 2) + part * 128);
    #pragma unroll
    for (int i = 0; i < 8; i++)
        asm volatile("cp.async.cg.shared.global [%0], [%1], 16, %2;"
                     :: "r"(dst + i * 16), "l"(src + i * 16), "r"(valid) : "memory");
    if (tid < BN) {
        int n2 = nbase + tid;
        float* y2b = (float*)(smem + OFF_Y2) + buf * BN;
        y2b[tid] = (n2 < NN) ? g_y2[h * NN + n2] : 3.0e37f;
    }
    asm volatile("cp.async.commit_group;" ::: "memory");
}

// ---------------------------------------------------------------------------
// K2: bf16 tensor GEMM + fused top-9. grid (64, H), 256 threads (2x4 warps).
// Warp computes 64q x 32n via 4x4 m16n8k16 tiles. key = y2[n] - 2*dot.
// ---------------------------------------------------------------------------
__global__ __launch_bounds__(256, 1)
void knn_kernel(const int* __restrict__ edges) {
    extern __shared__ char smem[];
    __nv_bfloat16* Qs = (__nv_bfloat16*)smem;
    float* Sb = (float*)(smem + OFF_SB);

    const int tid  = threadIdx.x;
    const int lane = tid & 31;
    const int wid  = tid >> 5;
    const int g    = lane >> 2;
    const int t4   = lane & 3;
    const int R0   = (wid >> 2) * 64;      // warp row: 0 or 64
    const int C0   = (wid & 3) * 32;       // warp col: 0,32,64,96

    const int h     = blockIdx.y;
    const int qbase = blockIdx.x * BQ;
    const __nv_bfloat16* Ebf = g_ebf + (size_t)h * NN * EMB;

    // ---- gather query tile (bf16 rows, padded stride) ----
    {
        int q = tid >> 1, part = tid & 1;
        int node = edges[qbase + q];       // flattened (2,4096) == query order
        const uint4* src = (const uint4*)(Ebf + (size_t)node * EMB) + part * 8;
        uint4* dst = (uint4*)(smem + q * (Q_LDE * 2) + part * 128);
        #pragma unroll
        for (int i = 0; i < 8; i++) dst[i] = src[i];
    }

    float bk[TOPK];
    int   bi[TOPK];
    #pragma unroll
    for (int r = 0; r < TOPK; r++) { bk[r] = 3.0e38f; bi[r] = 0; }

    prefetch_tile(Ebf, h, 0, smem, 0, tid);

    const uint32_t* Qw = (const uint32_t*)Qs;
    const int srow = tid & 127, shalf = tid >> 7;   // scan ownership: 2 thr/row

    for (int tIdx = 0; tIdx < NTILES; tIdx++) {
        const int nbase = tIdx * BN;
        const int cur   = tIdx & 1;
        if (tIdx + 1 < NTILES) {
            prefetch_tile(Ebf, h, nbase + BN, smem, cur ^ 1, tid);
            asm volatile("cp.async.wait_group 1;" ::: "memory");
        } else {
            asm volatile("cp.async.wait_group 0;" ::: "memory");
        }
        __syncthreads();   // tile cur + y2 visible; prev scan done (Sb free)

        const uint32_t* Nw = (const uint32_t*)(smem + OFF_NS + cur * NS_BYTES);
        const float*   y2c = (const float*)(smem + OFF_Y2) + cur * BN;

        // ---- tensor GEMM: 4x4 m16n8k16 per warp over K=128 ----
        float acc[4][4][4];
        #pragma unroll
        for (int mt = 0; mt < 4; mt++)
            #pragma unroll
            for (int nt = 0; nt < 4; nt++)
                #pragma unroll
                for (int r = 0; r < 4; r++) acc[mt][nt][r] = 0.0f;

        #pragma unroll
        for (int ks = 0; ks < 8; ks++) {
            const int kq = ks * 8;         // word offset (16 bf16 = 8 words)
            uint32_t a[4][4], b[4][2];
            #pragma unroll
            for (int mt = 0; mt < 4; mt++) {
                const uint32_t* p = Qw + (R0 + mt * 16 + g) * 68 + kq + t4;
                a[mt][0] = p[0];
                a[mt][1] = p[8 * 68];
                a[mt][2] = p[4];
                a[mt][3] = p[8 * 68 + 4];
            }
            #pragma unroll
            for (int nt = 0; nt < 4; nt++) {
                const uint32_t* p = Nw + (C0 + nt * 8 + g) * 68 + kq + t4;
                b[nt][0] = p[0];
                b[nt][1] = p[4];
            }
            #pragma unroll
            for (int mt = 0; mt < 4; mt++)
                #pragma unroll
                for (int nt = 0; nt < 4; nt++)
                    mma_bf16(acc[mt][nt], a[mt], b[nt]);
        }

        // ---- keys = y2 - 2*dot -> scan buffer ----
        #pragma unroll
        for (int nt = 0; nt < 4; nt++) {
            int col = C0 + nt * 8 + t4 * 2;
            float y0 = y2c[col], y1 = y2c[col + 1];
            #pragma unroll
            for (int mt = 0; mt < 4; mt++) {
                int row = R0 + mt * 16 + g;
                Sb[row * SB_LD + col]           = y0 - 2.0f * acc[mt][nt][0];
                Sb[row * SB_LD + col + 1]       = y1 - 2.0f * acc[mt][nt][1];
                Sb[(row + 8) * SB_LD + col]     = y0 - 2.0f * acc[mt][nt][2];
                Sb[(row + 8) * SB_LD + col + 1] = y1 - 2.0f * acc[mt][nt][3];
            }
        }
        __syncthreads();   // Sb visible

        // ---- 2 threads/row scan 64 cols each; rare sorted insertion ----
        {
            const float* rowp = Sb + srow * SB_LD + shalf * 64;
            const int ibase = nbase + shalf * 64;
            #pragma unroll 4
            for (int n = 0; n < 64; n++) {
                float key = rowp[n];
                if (key < bk[TOPK - 1]) {   // strict <: ties keep lower index
                    bk[TOPK - 1] = key;
                    bi[TOPK - 1] = ibase + n;
                    #pragma unroll
                    for (int r = TOPK - 1; r > 0; r--) {
                        if (bk[r] < bk[r - 1]) {
                            float tk = bk[r]; bk[r] = bk[r - 1]; bk[r - 1] = tk;
                            int   ti = bi[r]; bi[r] = bi[r - 1]; bi[r - 1] = ti;
                        }
                    }
                }
            }
        }
    }

    // ---- merge the two half-lists per row (exact (key,idx) lexicographic) ----
    __syncthreads();                        // scans done; Sb reusable as scratch
    float* mk = Sb;                         // [256][9] keys
    int*   mi = (int*)(Sb + 256 * TOPK);    // [256][9] indices
    #pragma unroll
    for (int r = 0; r < TOPK; r++) { mk[tid * TOPK + r] = bk[r]; mi[tid * TOPK + r] = bi[r]; }
    __syncthreads();
    if (tid < BQ) {
        const float* ka = mk + tid * TOPK;
        const int*   ia = mi + tid * TOPK;
        const float* kb = mk + (tid + 128) * TOPK;
        const int*   ib = mi + (tid + 128) * TOPK;
        int pa = 0, pb = 0;
        int sel[TOPK];
        #pragma unroll
        for (int r = 0; r < TOPK; r++) {
            bool ta = (ka[pa] < kb[pb]) || (ka[pa] == kb[pb] && ia[pa] < ib[pb]);
            sel[r] = ta ? ia[pa++] : ib[pb++];
        }
        int* out = g_samples + ((size_t)h * NQ + qbase + tid) * 8;
        #pragma unroll
        for (int r = 1; r < TOPK; r++) out[r - 1] = sel[r];  // drop rank 0 (self)
    }
}

// ---------------------------------------------------------------------------
// K3: epilogue. one block per batch edge, one warp per head. Exact fp32.
// ---------------------------------------------------------------------------
__global__ void epilogue_kernel(const float* __restrict__ embeds,
                                const float* __restrict__ field,
                                const float* __restrict__ unc,
                                const float* __restrict__ adj,
                                const int*   __restrict__ edges,
                                float*       __restrict__ out) {
    const int b    = blockIdx.x;
    const int h    = threadIdx.x >> 5;
    const int lane = threadIdx.x & 31;
    const int src  = edges[b];
    const int dst  = edges[NB + b];
    const float U  = unc[0];

    __shared__ float s_logit[H][16];
    __shared__ float s_dist[H][16];
    __shared__ float s_soft[H];

    const float* Eh = embeds + (size_t)h * NN * EMB;
    const float* Fh = field  + (size_t)h * NN * EMB;

    #pragma unroll
    for (int side = 0; side < 2; side++) {
        const int n     = (side == 0) ? src : dst;
        const int other = (side == 0) ? dst : src;
        const int* samp = g_samples + ((size_t)h * NQ + side * NB + b) * 8;
        float4 xn = ((const float4*)(Eh + (size_t)n * EMB))[lane];
        float4 gv = ((const float4*)(Fh + (size_t)other * EMB))[lane];
        for (int k = 0; k < 8; k++) {
            int s = samp[k];
            float4 es = ((const float4*)(Eh + (size_t)s * EMB))[lane];
            float dx = xn.x - es.x, dy = xn.y - es.y;
            float dz = xn.z - es.z, dw = xn.w - es.w;
            float dot = dx * gv.x + dy * gv.y + dz * gv.z + dw * gv.w;
            float ss  = dx * dx + dy * dy + dz * dz + dw * dw;
            #pragma unroll
            for (int o = 16; o > 0; o >>= 1) {
                dot += __shfl_xor_sync(0xffffffffu, dot, o);
                ss  += __shfl_xor_sync(0xffffffffu, ss,  o);
            }
            if (lane == 0) {
                float a = (side == 0) ? adj[(size_t)s * NN + other]
                                      : adj[(size_t)other * NN + s];
                s_logit[h][side * 8 + k] = dot + U * (a * 2.0f - 1.0f);
                s_dist [h][side * 8 + k] = sqrtf(ss);
            }
        }
    }
    __syncwarp();

    float w  = -3.0e38f, lg = 0.0f;
    if (lane < 16) { lg = s_logit[h][lane]; w = 1.0f - s_dist[h][lane]; }
    float m = w;
    #pragma unroll
    for (int o = 16; o > 0; o >>= 1) m = fmaxf(m, __shfl_xor_sync(0xffffffffu, m, o));
    m = fmaxf(m, 0.0f);
    float e   = (lane < 16) ? expf(w - m) : 0.0f;
    float num = e * lg;
    float den = e;
    #pragma unroll
    for (int o = 16; o > 0; o >>= 1) {
        num += __shfl_xor_sync(0xffffffffu, num, o);
        den += __shfl_xor_sync(0xffffffffu, den, o);
    }
    den += 8.0f * expf(-m);
    if (lane == 0) s_soft[h] = num / den;

    __syncthreads();
    if (threadIdx.x == 0) {
        float s = (s_soft[0] + s_soft[1] + s_soft[2] + s_soft[3]) * 0.25f;
        out[b] = 1.0f / (1.0f + expf(-s));
    }
}

// ---------------------------------------------------------------------------
extern "C" void kernel_launch(void* const* d_in, const int* in_sizes, int n_in,
                              void* d_out, int out_size) {
    (void)in_sizes; (void)n_in; (void)out_size;
    const float* embeds = (const float*)d_in[0];   // (4,10000,128) f32
    const float* field  = (const float*)d_in[1];   // (4,10000,128) f32
    const float* unc    = (const float*)d_in[2];   // (1,1,1) f32
    const float* adj    = (const float*)d_in[3];   // (10000,10000) f32
    const int*   edges  = (const int*)  d_in[4];   // (2,4096) i32
    float* out = (float*)d_out;                    // (4096,) f32

    cudaFuncSetAttribute(knn_kernel,
                         cudaFuncAttributeMaxDynamicSharedMemorySize, SMEM_BYTES);

    prep_kernel<<<(H * NN + 7) / 8, 256>>>(embeds);
    knn_kernel<<<dim3(NQ / BQ, H), 256, SMEM_BYTES>>>(edges);
    epilogue_kernel<<<NB, 128>>>(embeds, field, unc, adj, edges, out);
}

// round 8
// speedup vs baseline: 4.0687x; 1.1394x over previous
#include <cuda_runtime.h>
#include <cuda_fp8.h>
#include <math.h>
#include <stdint.h>

#define H        4
#define NN       10000
#define EMB      128
#define NB       4096
#define NQ       8192          // queries per head: [src(4096) | dst(4096)]
#define BQ       256           // queries per CTA -> 32x4 = 128 CTAs (single wave)
#define BN       128
#define NTILES   ((NN + BN - 1) / BN)   // 79
#define TOPK     9
#define RS       36            // smem row stride in words (144B): 36%32==4 -> conflict-free frags
#define SB_LD    132           // words; row start 16B-aligned; scan conflict-free

// smem byte offsets
#define QS_BYTES   (BQ * RS * 4)              // 36864
#define NS_BYTES   (BN * RS * 4)              // 18432 per buffer
#define OFF_N      (QS_BYTES)                 // 36864
#define OFF_SB     (QS_BYTES + 2 * NS_BYTES)  // 73728
#define SB_BYTES   (BQ * SB_LD * 4)           // 135168
#define OFF_Y2     (OFF_SB + SB_BYTES)        // 208896
#define SMEM_BYTES (OFF_Y2 + 4 * BN * 4)      // 210944

__device__ uint8_t g_e8[(size_t)H * NN * EMB];
__device__ float   g_y2[H * NN];
__device__ int     g_samples[H * NQ * 8];

// ---------------------------------------------------------------------------
// K1: convert embeds -> fp8 e4m3; y2 from the DEQUANTIZED values (fp32).
// one warp per row.
// ---------------------------------------------------------------------------
__global__ void prep_kernel(const float* __restrict__ embeds) {
    int gid  = blockIdx.x * 8 + (threadIdx.x >> 5);
    int lane = threadIdx.x & 31;
    if (gid >= H * NN) return;
    float4 v = ((const float4*)(embeds + (size_t)gid * EMB))[lane];
    __nv_fp8_e4m3 q0(v.x), q1(v.y), q2(v.z), q3(v.w);
    uint32_t packed = (uint32_t)q0.__x | ((uint32_t)q1.__x << 8)
                    | ((uint32_t)q2.__x << 16) | ((uint32_t)q3.__x << 24);
    ((uint32_t*)(g_e8 + (size_t)gid * EMB))[lane] = packed;
    float a = (float)q0, b = (float)q1, c = (float)q2, d = (float)q3;
    float s = a * a + b * b + c * c + d * d;
    #pragma unroll
    for (int o = 16; o > 0; o >>= 1) s += __shfl_xor_sync(0xffffffffu, s, o);
    if (lane == 0) g_y2[gid] = s;
}

// ---------------------------------------------------------------------------
__device__ __forceinline__ void mma_e4m3(float* c, const uint32_t* a, const uint32_t* b) {
    asm volatile(
        "mma.sync.aligned.m16n8k32.row.col.f32.e4m3.e4m3.f32 "
        "{%0,%1,%2,%3}, {%4,%5,%6,%7}, {%8,%9}, {%0,%1,%2,%3};"
        : "+f"(c[0]), "+f"(c[1]), "+f"(c[2]), "+f"(c[3])
        : "r"(a[0]), "r"(a[1]), "r"(a[2]), "r"(a[3]), "r"(b[0]), "r"(b[1]));
}

__device__ __forceinline__ void prefetch_tile(const uint8_t* __restrict__ E8,
                                              int h, int nbase, char* smem,
                                              int buf, int slot, int tid) {
    char* nb = smem + OFF_N + buf * NS_BYTES;
    int row  = tid >> 1;
    int part = tid & 1;
    int node = nbase + row;
    int valid = (node < NN) ? 16 : 0;
    const char* src = (const char*)(E8 + (size_t)(valid ? node : 0) * EMB) + part * 64;
    uint32_t dst = (uint32_t)__cvta_generic_to_shared(nb + row * (RS * 4) + part * 64);
    #pragma unroll
    for (int i = 0; i < 4; i++)
        asm volatile("cp.async.cg.shared.global [%0], [%1], 16, %2;"
                     :: "r"(dst + i * 16), "l"(src + i * 16), "r"(valid) : "memory");
    if (tid < BN) {
        int n2 = nbase + tid;
        float* y2s = (float*)(smem + OFF_Y2) + slot * BN;
        y2s[tid] = (n2 < NN) ? g_y2[h * NN + n2] : 3.0e37f;
    }
    asm volatile("cp.async.commit_group;" ::: "memory");
}

// ---------------------------------------------------------------------------
// K2: fp8 tensor GEMM + fused top-9. grid (32, H), 256 threads (4x2 warps).
// Warp computes 64q x 64n via 4x8 m16n8k32 tiles over K=128 (4 k-steps).
// key = y2[n] - 2*dot  (rank-equivalent to quantized d2).
// ---------------------------------------------------------------------------
__global__ __launch_bounds__(256, 1)
void knn_kernel(const int* __restrict__ edges) {
    extern __shared__ __align__(16) char smem[];
    float* Sb = (float*)(smem + OFF_SB);

    const int tid  = threadIdx.x;
    const int lane = tid & 31;
    const int wid  = tid >> 5;
    const int g    = lane >> 2;            // 0..7
    const int t4   = lane & 3;             // 0..3
    const int R0   = (wid >> 1) * 64;      // warp row: 0,64,128,192
    const int C0   = (wid & 1) * 64;       // warp col: 0,64

    const int h     = blockIdx.y;
    const int qbase = blockIdx.x * BQ;
    const uint8_t* E8 = g_e8 + (size_t)h * NN * EMB;

    // ---- gather query tile: one thread per row (fp8, padded stride) ----
    {
        int node = edges[qbase + tid];     // flattened (2,4096) == query order
        const uint4* src = (const uint4*)(E8 + (size_t)node * EMB);
        uint4* dst = (uint4*)(smem + tid * (RS * 4));
        #pragma unroll
        for (int i = 0; i < 8; i++) dst[i] = src[i];
    }

    float bk[TOPK];
    int   bi[TOPK];
    #pragma unroll
    for (int r = 0; r < TOPK; r++) { bk[r] = 3.0e38f; bi[r] = 0; }

    prefetch_tile(E8, h, 0, smem, 0, 0, tid);
    prefetch_tile(E8, h, BN, smem, 1, 1, tid);

    const uint32_t* Qw = (const uint32_t*)smem;
    const float* y2all = (const float*)(smem + OFF_Y2);

    for (int t = 0; t < NTILES; t++) {
        const int nbase = t * BN;
        if (t + 2 < NTILES)
            asm volatile("cp.async.wait_group 1;" ::: "memory");
        else
            asm volatile("cp.async.wait_group 0;" ::: "memory");
        __syncthreads();   // tile t + y2 visible; prev scan done (Sb free)

        const uint32_t* Nw = (const uint32_t*)(smem + OFF_N + (t & 1) * NS_BYTES);
        const float*   y2s = y2all + (t & 3) * BN;

        // ---- tensor GEMM: 4x8 m16n8k32 per warp, 4 k-steps ----
        float acc[4][8][4];
        #pragma unroll
        for (int mt = 0; mt < 4; mt++)
            #pragma unroll
            for (int nt = 0; nt < 8; nt++)
                #pragma unroll
                for (int r = 0; r < 4; r++) acc[mt][nt][r] = 0.0f;

        #pragma unroll
        for (int ks = 0; ks < 4; ks++) {
            const int kw = ks * 8;         // word offset (32 e4m3 = 8 words)
            uint32_t a[4][4], b[8][2];
            #pragma unroll
            for (int mt = 0; mt < 4; mt++) {
                const uint32_t* p = Qw + (R0 + mt * 16 + g) * RS + kw + t4;
                a[mt][0] = p[0];
                a[mt][1] = p[8 * RS];
                a[mt][2] = p[4];
                a[mt][3] = p[8 * RS + 4];
            }
            #pragma unroll
            for (int nt = 0; nt < 8; nt++) {
                const uint32_t* p = Nw + (C0 + nt * 8 + g) * RS + kw + t4;
                b[nt][0] = p[0];
                b[nt][1] = p[4];
            }
            #pragma unroll
            for (int mt = 0; mt < 4; mt++)
                #pragma unroll
                for (int nt = 0; nt < 8; nt++)
                    mma_e4m3(acc[mt][nt], a[mt], b[nt]);
        }

        // ---- keys = y2 - 2*dot -> scan buffer (float2 stores) ----
        #pragma unroll
        for (int nt = 0; nt < 8; nt++) {
            int col = C0 + nt * 8 + t4 * 2;
            float y0 = y2s[col], y1 = y2s[col + 1];
            #pragma unroll
            for (int mt = 0; mt < 4; mt++) {
                int row = R0 + mt * 16 + g;
                *(float2*)(Sb + row * SB_LD + col) =
                    make_float2(y0 - 2.0f * acc[mt][nt][0], y1 - 2.0f * acc[mt][nt][1]);
                *(float2*)(Sb + (row + 8) * SB_LD + col) =
                    make_float2(y0 - 2.0f * acc[mt][nt][2], y1 - 2.0f * acc[mt][nt][3]);
            }
        }
        __syncthreads();   // Sb visible; N[t&1] free

        // ---- prefetch t+2 into the freed node buffer ----
        if (t + 2 < NTILES)
            prefetch_tile(E8, h, nbase + 2 * BN, smem, t & 1, (t + 2) & 3, tid);

        // ---- each thread scans its own row (float4, conflict-free) ----
        {
            const float4* rowp = (const float4*)(Sb + tid * SB_LD);
            #pragma unroll 4
            for (int n4 = 0; n4 < BN / 4; n4++) {
                float4 kv = rowp[n4];
                float ks4[4] = {kv.x, kv.y, kv.z, kv.w};
                #pragma unroll
                for (int u = 0; u < 4; u++) {
                    float key = ks4[u];
                    if (key < bk[TOPK - 1]) {   // strict <: ties keep lower index
                        bk[TOPK - 1] = key;
                        bi[TOPK - 1] = nbase + n4 * 4 + u;
                        #pragma unroll
                        for (int r = TOPK - 1; r > 0; r--) {
                            if (bk[r] < bk[r - 1]) {
                                float tk = bk[r]; bk[r] = bk[r - 1]; bk[r - 1] = tk;
                                int   ti = bi[r]; bi[r] = bi[r - 1]; bi[r - 1] = ti;
                            }
                        }
                    }
                }
            }
        }
    }

    // ---- emit ranks 1..8 (rank 0 == self); thread owns query row tid ----
    {
        int* out = g_samples + ((size_t)h * NQ + qbase + tid) * 8;
        #pragma unroll
        for (int r = 1; r < TOPK; r++) out[r - 1] = bi[r];
    }
}

// ---------------------------------------------------------------------------
// K3: epilogue. one block per batch edge, one warp per head. Exact fp32.
// ---------------------------------------------------------------------------
__global__ void epilogue_kernel(const float* __restrict__ embeds,
                                const float* __restrict__ field,
                                const float* __restrict__ unc,
                                const float* __restrict__ adj,
                                const int*   __restrict__ edges,
                                float*       __restrict__ out) {
    const int b    = blockIdx.x;
    const int h    = threadIdx.x >> 5;
    const int lane = threadIdx.x & 31;
    const int src  = edges[b];
    const int dst  = edges[NB + b];
    const float U  = unc[0];

    __shared__ float s_logit[H][16];
    __shared__ float s_dist[H][16];
    __shared__ float s_soft[H];

    const float* Eh = embeds + (size_t)h * NN * EMB;
    const float* Fh = field  + (size_t)h * NN * EMB;

    #pragma unroll
    for (int side = 0; side < 2; side++) {
        const int n     = (side == 0) ? src : dst;
        const int other = (side == 0) ? dst : src;
        const int* samp = g_samples + ((size_t)h * NQ + side * NB + b) * 8;
        float4 xn = ((const float4*)(Eh + (size_t)n * EMB))[lane];
        float4 gv = ((const float4*)(Fh + (size_t)other * EMB))[lane];
        for (int k = 0; k < 8; k++) {
            int s = samp[k];
            float4 es = ((const float4*)(Eh + (size_t)s * EMB))[lane];
            float dx = xn.x - es.x, dy = xn.y - es.y;
            float dz = xn.z - es.z, dw = xn.w - es.w;
            float dot = dx * gv.x + dy * gv.y + dz * gv.z + dw * gv.w;
            float ss  = dx * dx + dy * dy + dz * dz + dw * dw;
            #pragma unroll
            for (int o = 16; o > 0; o >>= 1) {
                dot += __shfl_xor_sync(0xffffffffu, dot, o);
                ss  += __shfl_xor_sync(0xffffffffu, ss,  o);
            }
            if (lane == 0) {
                float a = (side == 0) ? adj[(size_t)s * NN + other]
                                      : adj[(size_t)other * NN + s];
                s_logit[h][side * 8 + k] = dot + U * (a * 2.0f - 1.0f);
                s_dist [h][side * 8 + k] = sqrtf(ss);
            }
        }
    }
    __syncwarp();

    float w  = -3.0e38f, lg = 0.0f;
    if (lane < 16) { lg = s_logit[h][lane]; w = 1.0f - s_dist[h][lane]; }
    float m = w;
    #pragma unroll
    for (int o = 16; o > 0; o >>= 1) m = fmaxf(m, __shfl_xor_sync(0xffffffffu, m, o));
    m = fmaxf(m, 0.0f);
    float e   = (lane < 16) ? expf(w - m) : 0.0f;
    float num = e * lg;
    float den = e;
    #pragma unroll
    for (int o = 16; o > 0; o >>= 1) {
        num += __shfl_xor_sync(0xffffffffu, num, o);
        den += __shfl_xor_sync(0xffffffffu, den, o);
    }
    den += 8.0f * expf(-m);
    if (lane == 0) s_soft[h] = num / den;

    __syncthreads();
    if (threadIdx.x == 0) {
        float s = (s_soft[0] + s_soft[1] + s_soft[2] + s_soft[3]) * 0.25f;
        out[b] = 1.0f / (1.0f + expf(-s));
    }
}

// ---------------------------------------------------------------------------
extern "C" void kernel_launch(void* const* d_in, const int* in_sizes, int n_in,
                              void* d_out, int out_size) {
    (void)in_sizes; (void)n_in; (void)out_size;
    const float* embeds = (const float*)d_in[0];   // (4,10000,128) f32
    const float* field  = (const float*)d_in[1];   // (4,10000,128) f32
    const float* unc    = (const float*)d_in[2];   // (1,1,1) f32
    const float* adj    = (const float*)d_in[3];   // (10000,10000) f32
    const int*   edges  = (const int*)  d_in[4];   // (2,4096) i32
    float* out = (float*)d_out;                    // (4096,) f32

    cudaFuncSetAttribute(knn_kernel,
                         cudaFuncAttributeMaxDynamicSharedMemorySize, SMEM_BYTES);

    prep_kernel<<<(H * NN + 7) / 8, 256>>>(embeds);
    knn_kernel<<<dim3(NQ / BQ, H), 256, SMEM_BYTES>>>(edges);
    epilogue_kernel<<<NB, 128>>>(embeds, field, unc, adj, edges, out);
}

// round 9
// speedup vs baseline: 4.8120x; 1.1827x over previous
#include <cuda_runtime.h>
#include <cuda_fp8.h>
#include <math.h>
#include <stdint.h>

#define H        4
#define NN       10000
#define EMB      128
#define NB       4096
#define NQ       8192          // queries per head: [src(4096) | dst(4096)]
#define BQ       256           // queries per CTA -> 32x4 = 128 CTAs (single wave)
#define BN       128
#define NTILES   ((NN + BN - 1) / BN)   // 79
#define TOPK     9
#define NT       512           // threads per CTA (16 warps, 4 per SMSP)
#define RS       36            // smem row stride words (144B): 36%32==4 -> conflict-free frags
#define SB_LD    132           // words; float4 row scan conflict-free (4L%32 covers all banks)

// smem byte offsets
#define QS_BYTES   (BQ * RS * 4)              // 36864
#define NS_BYTES   (BN * RS * 4)              // 18432 per buffer
#define OFF_N      (QS_BYTES)                 // 36864
#define OFF_SB     (QS_BYTES + 2 * NS_BYTES)  // 73728
#define SB_BYTES   (BQ * SB_LD * 4)           // 135168
#define OFF_Y2     (OFF_SB + SB_BYTES)        // 208896
#define SMEM_BYTES (OFF_Y2 + 4 * BN * 4)      // 210944

__device__ uint8_t g_e8[(size_t)H * NN * EMB];
__device__ float   g_y2[H * NN];
__device__ int     g_samples[H * NQ * 8];

// ---------------------------------------------------------------------------
// K1: convert embeds -> fp8 e4m3; y2 from the DEQUANTIZED values (fp32).
// ---------------------------------------------------------------------------
__global__ void prep_kernel(const float* __restrict__ embeds) {
    int gid  = blockIdx.x * 8 + (threadIdx.x >> 5);
    int lane = threadIdx.x & 31;
    if (gid >= H * NN) return;
    float4 v = ((const float4*)(embeds + (size_t)gid * EMB))[lane];
    __nv_fp8_e4m3 q0(v.x), q1(v.y), q2(v.z), q3(v.w);
    uint32_t packed = (uint32_t)q0.__x | ((uint32_t)q1.__x << 8)
                    | ((uint32_t)q2.__x << 16) | ((uint32_t)q3.__x << 24);
    ((uint32_t*)(g_e8 + (size_t)gid * EMB))[lane] = packed;
    float a = (float)q0, b = (float)q1, c = (float)q2, d = (float)q3;
    float s = a * a + b * b + c * c + d * d;
    #pragma unroll
    for (int o = 16; o > 0; o >>= 1) s += __shfl_xor_sync(0xffffffffu, s, o);
    if (lane == 0) g_y2[gid] = s;
}

// ---------------------------------------------------------------------------
__device__ __forceinline__ void mma_e4m3(float* c, const uint32_t* a, const uint32_t* b) {
    asm volatile(
        "mma.sync.aligned.m16n8k32.row.col.f32.e4m3.e4m3.f32 "
        "{%0,%1,%2,%3}, {%4,%5,%6,%7}, {%8,%9}, {%0,%1,%2,%3};"
        : "+f"(c[0]), "+f"(c[1]), "+f"(c[2]), "+f"(c[3])
        : "r"(a[0]), "r"(a[1]), "r"(a[2]), "r"(a[3]), "r"(b[0]), "r"(b[1]));
}

__device__ __forceinline__ void prefetch_tile(const uint8_t* __restrict__ E8,
                                              int h, int nbase, char* smem,
                                              int buf, int slot, int tid) {
    char* nb = smem + OFF_N + buf * NS_BYTES;
    int row  = tid >> 2;          // 128 rows, 4 threads/row
    int part = tid & 3;           // 32B each
    int node = nbase + row;
    int valid = (node < NN) ? 16 : 0;
    const char* src = (const char*)(E8 + (size_t)(valid ? node : 0) * EMB) + part * 32;
    uint32_t dst = (uint32_t)__cvta_generic_to_shared(nb + row * (RS * 4) + part * 32);
    #pragma unroll
    for (int i = 0; i < 2; i++)
        asm volatile("cp.async.cg.shared.global [%0], [%1], 16, %2;"
                     :: "r"(dst + i * 16), "l"(src + i * 16), "r"(valid) : "memory");
    if (tid < BN) {
        int n2 = nbase + tid;
        float* y2s = (float*)(smem + OFF_Y2) + slot * BN;
        y2s[tid] = (n2 < NN) ? g_y2[h * NN + n2] : 3.0e37f;
    }
    asm volatile("cp.async.commit_group;" ::: "memory");
}

// ---------------------------------------------------------------------------
// K2: fp8 tensor GEMM + fused top-9. grid (32, H), 512 threads (4x4 warps).
// Warp computes 64q x 32n via 4x4 m16n8k32 tiles over K=128 (4 k-steps).
// key = y2[n] - 2*dot (rank-equivalent to quantized d2).
// ---------------------------------------------------------------------------
__global__ __launch_bounds__(NT, 1)
void knn_kernel(const int* __restrict__ edges) {
    extern __shared__ __align__(16) char smem[];
    float* Sb = (float*)(smem + OFF_SB);

    const int tid  = threadIdx.x;
    const int lane = tid & 31;
    const int wid  = tid >> 5;
    const int g    = lane >> 2;            // 0..7
    const int t4   = lane & 3;             // 0..3
    const int R0   = (wid >> 2) * 64;      // warp row: 0,64,128,192
    const int C0   = (wid & 3) * 32;       // warp col: 0,32,64,96

    const int h     = blockIdx.y;
    const int qbase = blockIdx.x * BQ;
    const uint8_t* E8 = g_e8 + (size_t)h * NN * EMB;

    // ---- gather query tile: 2 threads per row (fp8, padded stride) ----
    {
        int row = tid >> 1, part = tid & 1;
        int node = edges[qbase + row];     // flattened (2,4096) == query order
        const uint4* src = (const uint4*)(E8 + (size_t)node * EMB + part * 64);
        uint4* dst = (uint4*)(smem + row * (RS * 4) + part * 64);
        #pragma unroll
        for (int i = 0; i < 4; i++) dst[i] = src[i];
    }

    float bk[TOPK];
    int   bi[TOPK];
    #pragma unroll
    for (int r = 0; r < TOPK; r++) { bk[r] = 3.0e38f; bi[r] = 0; }

    prefetch_tile(E8, h, 0, smem, 0, 0, tid);
    prefetch_tile(E8, h, BN, smem, 1, 1, tid);

    const uint32_t* Qw = (const uint32_t*)smem;
    const float* y2all = (const float*)(smem + OFF_Y2);
    const int srow = tid & 255, shalf = tid >> 8;   // scan: 2 threads/row

    for (int t = 0; t < NTILES; t++) {
        const int nbase = t * BN;
        if (t + 2 < NTILES)
            asm volatile("cp.async.wait_group 1;" ::: "memory");
        else
            asm volatile("cp.async.wait_group 0;" ::: "memory");
        __syncthreads();   // tile t + y2 visible; prev scan done (Sb free)

        const uint32_t* Nw = (const uint32_t*)(smem + OFF_N + (t & 1) * NS_BYTES);
        const float*   y2s = y2all + (t & 3) * BN;

        // ---- tensor GEMM: 4x4 m16n8k32 per warp, 4 k-steps ----
        float acc[4][4][4];
        #pragma unroll
        for (int mt = 0; mt < 4; mt++)
            #pragma unroll
            for (int nt = 0; nt < 4; nt++)
                #pragma unroll
                for (int r = 0; r < 4; r++) acc[mt][nt][r] = 0.0f;

        #pragma unroll
        for (int ks = 0; ks < 4; ks++) {
            const int kw = ks * 8;         // word offset (32 e4m3 = 8 words)
            uint32_t a[4][4], b[4][2];
            #pragma unroll
            for (int mt = 0; mt < 4; mt++) {
                const uint32_t* p = Qw + (R0 + mt * 16 + g) * RS + kw + t4;
                a[mt][0] = p[0];
                a[mt][1] = p[8 * RS];
                a[mt][2] = p[4];
                a[mt][3] = p[8 * RS + 4];
            }
            #pragma unroll
            for (int nt = 0; nt < 4; nt++) {
                const uint32_t* p = Nw + (C0 + nt * 8 + g) * RS + kw + t4;
                b[nt][0] = p[0];
                b[nt][1] = p[4];
            }
            #pragma unroll
            for (int mt = 0; mt < 4; mt++)
                #pragma unroll
                for (int nt = 0; nt < 4; nt++)
                    mma_e4m3(acc[mt][nt], a[mt], b[nt]);
        }

        // ---- keys = y2 - 2*dot -> scan buffer (float2 stores) ----
        #pragma unroll
        for (int nt = 0; nt < 4; nt++) {
            int col = C0 + nt * 8 + t4 * 2;
            float y0 = y2s[col], y1 = y2s[col + 1];
            #pragma unroll
            for (int mt = 0; mt < 4; mt++) {
                int row = R0 + mt * 16 + g;
                *(float2*)(Sb + row * SB_LD + col) =
                    make_float2(y0 - 2.0f * acc[mt][nt][0], y1 - 2.0f * acc[mt][nt][1]);
                *(float2*)(Sb + (row + 8) * SB_LD + col) =
                    make_float2(y0 - 2.0f * acc[mt][nt][2], y1 - 2.0f * acc[mt][nt][3]);
            }
        }
        __syncthreads();   // Sb visible; N[t&1] free

        // ---- prefetch t+2 into the freed node buffer ----
        if (t + 2 < NTILES)
            prefetch_tile(E8, h, nbase + 2 * BN, smem, t & 1, (t + 2) & 3, tid);

        // ---- scan 64 cols/thread: float4 + fmin early-out ----
        {
            const float4* rowp = (const float4*)(Sb + srow * SB_LD + shalf * 64);
            const int ibase = nbase + shalf * 64;
            #pragma unroll 4
            for (int n4 = 0; n4 < 16; n4++) {
                float4 kv = rowp[n4];
                float qmin = fminf(fminf(kv.x, kv.y), fminf(kv.z, kv.w));
                if (qmin < bk[TOPK - 1]) {      // rare once threshold tightens
                    float ks4[4] = {kv.x, kv.y, kv.z, kv.w};
                    #pragma unroll
                    for (int u = 0; u < 4; u++) {
                        float key = ks4[u];
                        if (key < bk[TOPK - 1]) {   // strict <: ties keep lower idx
                            bk[TOPK - 1] = key;
                            bi[TOPK - 1] = ibase + n4 * 4 + u;
                            #pragma unroll
                            for (int r = TOPK - 1; r > 0; r--) {
                                if (bk[r] < bk[r - 1]) {
                                    float tk = bk[r]; bk[r] = bk[r - 1]; bk[r - 1] = tk;
                                    int   ti = bi[r]; bi[r] = bi[r - 1]; bi[r - 1] = ti;
                                }
                            }
                        }
                    }
                }
            }
        }
    }

    // ---- merge the two half-lists per row (exact (key,idx) lexicographic) ----
    __syncthreads();                        // scans done; Sb reusable as scratch
    float* mk = Sb;                         // [512][9] keys
    int*   mi = (int*)(Sb + NT * TOPK);     // [512][9] indices
    #pragma unroll
    for (int r = 0; r < TOPK; r++) { mk[tid * TOPK + r] = bk[r]; mi[tid * TOPK + r] = bi[r]; }
    __syncthreads();
    if (tid < BQ) {
        const float* ka = mk + tid * TOPK;
        const int*   ia = mi + tid * TOPK;
        const float* kb = mk + (tid + 256) * TOPK;
        const int*   ib = mi + (tid + 256) * TOPK;
        int pa = 0, pb = 0;
        int sel[TOPK];
        #pragma unroll
        for (int r = 0; r < TOPK; r++) {
            bool ta = (ka[pa] < kb[pb]) || (ka[pa] == kb[pb] && ia[pa] < ib[pb]);
            sel[r] = ta ? ia[pa++] : ib[pb++];
        }
        int* out = g_samples + ((size_t)h * NQ + qbase + tid) * 8;
        #pragma unroll
        for (int r = 1; r < TOPK; r++) out[r - 1] = sel[r];  // drop rank 0 (self)
    }
}

// ---------------------------------------------------------------------------
// K3: epilogue. one block per batch edge, one warp per head. Exact fp32.
// ---------------------------------------------------------------------------
__global__ void epilogue_kernel(const float* __restrict__ embeds,
                                const float* __restrict__ field,
                                const float* __restrict__ unc,
                                const float* __restrict__ adj,
                                const int*   __restrict__ edges,
                                float*       __restrict__ out) {
    const int b    = blockIdx.x;
    const int h    = threadIdx.x >> 5;
    const int lane = threadIdx.x & 31;
    const int src  = edges[b];
    const int dst  = edges[NB + b];
    const float U  = unc[0];

    __shared__ float s_logit[H][16];
    __shared__ float s_dist[H][16];
    __shared__ float s_soft[H];

    const float* Eh = embeds + (size_t)h * NN * EMB;
    const float* Fh = field  + (size_t)h * NN * EMB;

    #pragma unroll
    for (int side = 0; side < 2; side++) {
        const int n     = (side == 0) ? src : dst;
        const int other = (side == 0) ? dst : src;
        const int* samp = g_samples + ((size_t)h * NQ + side * NB + b) * 8;
        float4 xn = ((const float4*)(Eh + (size_t)n * EMB))[lane];
        float4 gv = ((const float4*)(Fh + (size_t)other * EMB))[lane];
        for (int k = 0; k < 8; k++) {
            int s = samp[k];
            float4 es = ((const float4*)(Eh + (size_t)s * EMB))[lane];
            float dx = xn.x - es.x, dy = xn.y - es.y;
            float dz = xn.z - es.z, dw = xn.w - es.w;
            float dot = dx * gv.x + dy * gv.y + dz * gv.z + dw * gv.w;
            float ss  = dx * dx + dy * dy + dz * dz + dw * dw;
            #pragma unroll
            for (int o = 16; o > 0; o >>= 1) {
                dot += __shfl_xor_sync(0xffffffffu, dot, o);
                ss  += __shfl_xor_sync(0xffffffffu, ss,  o);
            }
            if (lane == 0) {
                float a = (side == 0) ? adj[(size_t)s * NN + other]
                                      : adj[(size_t)other * NN + s];
                s_logit[h][side * 8 + k] = dot + U * (a * 2.0f - 1.0f);
                s_dist [h][side * 8 + k] = sqrtf(ss);
            }
        }
    }
    __syncwarp();

    float w  = -3.0e38f, lg = 0.0f;
    if (lane < 16) { lg = s_logit[h][lane]; w = 1.0f - s_dist[h][lane]; }
    float m = w;
    #pragma unroll
    for (int o = 16; o > 0; o >>= 1) m = fmaxf(m, __shfl_xor_sync(0xffffffffu, m, o));
    m = fmaxf(m, 0.0f);
    float e   = (lane < 16) ? expf(w - m) : 0.0f;
    float num = e * lg;
    float den = e;
    #pragma unroll
    for (int o = 16; o > 0; o >>= 1) {
        num += __shfl_xor_sync(0xffffffffu, num, o);
        den += __shfl_xor_sync(0xffffffffu, den, o);
    }
    den += 8.0f * expf(-m);
    if (lane == 0) s_soft[h] = num / den;

    __syncthreads();
    if (threadIdx.x == 0) {
        float s = (s_soft[0] + s_soft[1] + s_soft[2] + s_soft[3]) * 0.25f;
        out[b] = 1.0f / (1.0f + expf(-s));
    }
}

// ---------------------------------------------------------------------------
extern "C" void kernel_launch(void* const* d_in, const int* in_sizes, int n_in,
                              void* d_out, int out_size) {
    (void)in_sizes; (void)n_in; (void)out_size;
    const float* embeds = (const float*)d_in[0];   // (4,10000,128) f32
    const float* field  = (const float*)d_in[1];   // (4,10000,128) f32
    const float* unc    = (const float*)d_in[2];   // (1,1,1) f32
    const float* adj    = (const float*)d_in[3];   // (10000,10000) f32
    const int*   edges  = (const int*)  d_in[4];   // (2,4096) i32
    float* out = (float*)d_out;                    // (4096,) f32

    cudaFuncSetAttribute(knn_kernel,
                         cudaFuncAttributeMaxDynamicSharedMemorySize, SMEM_BYTES);

    prep_kernel<<<(H * NN + 7) / 8, 256>>>(embeds);
    knn_kernel<<<dim3(NQ / BQ, H), NT, SMEM_BYTES>>>(edges);
    epilogue_kernel<<<NB, 128>>>(embeds, field, unc, adj, edges, out);
}